// round 8
// baseline (speedup 1.0000x reference)
#include <cuda_runtime.h>
#include <math.h>

// Problem constants
#define WINDOW 40
#define E 8
#define FDIM 64
#define TDIM 64
#define KERNEL 5
#define IN_CH 144          // F + 10*E
#define LIN_IN 36          // WINDOW + 1 - KERNEL
#define NCOL 320           // WINDOW * E rank columns
#define NMAX 8192
#define NSAMP 8000         // compile-time N (asserted at launch)

// Scratch (device globals — no allocation allowed)
__device__ float g_cols[(size_t)NCOL * NMAX];   // [col][n] gathered last-window values
__device__ float g_rank[(size_t)NMAX * NCOL];   // [n][col] rank/N (coalesced main reads)

// ---------------------------------------------------------------------------
// Kernel 1: gather x[:, 24+t, 0:8] -> g_cols[(t*8+f)][n]  (proven 12us)
// ---------------------------------------------------------------------------
__global__ void gather_kernel(const float* __restrict__ x, int N) {
    __shared__ float tile[256][9];   // pad 9 -> conflict-free both phases
    const int t  = blockIdx.y;
    const int n0 = blockIdx.x * 256;
    const int tid = threadIdx.x;
    const int n = n0 + tid;
    if (n < N) {
        const float4* p = (const float4*)(x + (size_t)n * (TDIM * FDIM) + (24 + t) * FDIM);
        float4 a = p[0], b = p[1];
        tile[tid][0] = a.x; tile[tid][1] = a.y; tile[tid][2] = a.z; tile[tid][3] = a.w;
        tile[tid][4] = b.x; tile[tid][5] = b.y; tile[tid][6] = b.z; tile[tid][7] = b.w;
    }
    __syncthreads();
    #pragma unroll
    for (int idx = tid; idx < 8 * 256; idx += 256) {
        int f = idx >> 8, s = idx & 255;
        int nn = n0 + s;
        if (nn < N) g_cols[(size_t)(t * 8 + f) * NMAX + nn] = tile[s][f];
    }
}

// ---------------------------------------------------------------------------
// Kernel 2: exact stable descending rank. Two-pass over L2-resident g_cols:
//   pass A: 14-bit histogram (interleaved conflict-free cursor layout)
//   scan   : exclusive over 16384 bins (conflict-free via phys mapping)
//   pass B: re-read, scatter KEYS + indices into sorted-grouped position
//   rank   : sorted-order walk, warp-coherent buckets, broadcast LDS compares
// Bit-exact vs argsort(argsort(-last)). 80.8KB smem -> 2 blocks/SM.
// ---------------------------------------------------------------------------
#define RT 512
#define NBIN 16384                  // 14-bit buckets of the ascending key
#define CURW (NBIN / 2)             // 8192 u16-pair words
// logical word L holds bins {2L, 2L+1}; thread t owns L in [t*16, t*16+16)
// phys(L) = (L&15)*512 + (L>>4)  -> scan accesses stride-512 = conflict-free
__device__ __forceinline__ int cphys(unsigned int L) {
    return (int)(((L & 15u) << 9) | (L >> 4));
}
// smem: keys u32[NSAMP] | cur u32[CURW] | order u16[NSAMP]
#define OFF_CUR  (NSAMP * 4)                 // 32000
#define OFF_ORD  (OFF_CUR + CURW * 4)        // 64768
#define RANK_SMEM (OFF_ORD + NSAMP * 2)      // 80768 bytes

__global__ __launch_bounds__(RT) void rank_kernel() {
    extern __shared__ unsigned char sm[];
    unsigned int*   keys  = (unsigned int*)sm;             // sorted-grouped keys
    unsigned int*   cur   = (unsigned int*)(sm + OFF_CUR); // packed counts->cursors
    unsigned short* order = (unsigned short*)(sm + OFF_ORD);
    __shared__ unsigned int aux[16];

    const int c    = blockIdx.x;
    const int tid  = threadIdx.x;
    const int lane = tid & 31, wrp = tid >> 5;
    const float* col = &g_cols[(size_t)c * NMAX];

    for (int i = tid; i < CURW; i += RT) cur[i] = 0u;
    __syncthreads();

    // ---- pass A: histogram ----
    for (int i = tid; i < NSAMP; i += RT) {
        unsigned int u = __float_as_uint(col[i]);
        unsigned int mono = u ^ ((u >> 31) ? 0xFFFFFFFFu : 0x80000000u);
        unsigned int k = ~mono;                  // ascending k == descending value
        unsigned int b = k >> 18;                // top 14 bits
        atomicAdd(&cur[cphys(b >> 1)], 1u << ((b & 1) * 16));
    }
    __syncthreads();

    // ---- exclusive scan: thread owns 16 words (32 bins), conflict-free ----
    unsigned int hv[16];
    unsigned int tsum = 0;
    #pragma unroll
    for (int w = 0; w < 16; ++w) {
        hv[w] = cur[w * 512 + tid];
        tsum += (hv[w] & 0xFFFFu) + (hv[w] >> 16);
    }
    unsigned int v = tsum;
    #pragma unroll
    for (int d = 1; d < 32; d <<= 1) {
        unsigned int t2 = __shfl_up_sync(0xFFFFFFFFu, v, d);
        if (lane >= d) v += t2;
    }
    if (lane == 31) aux[wrp] = v;
    __syncthreads();
    if (wrp == 0 && lane < 16) {
        unsigned int s = aux[lane];
        #pragma unroll
        for (int d = 1; d < 16; d <<= 1) {
            unsigned int t2 = __shfl_up_sync(0x0000FFFFu, s, d);
            if (lane >= d) s += t2;
        }
        aux[lane] = s;
    }
    __syncthreads();
    unsigned int run = v - tsum + (wrp ? aux[wrp - 1] : 0u);  // exclusive prefix
    #pragma unroll
    for (int w = 0; w < 16; ++w) {
        unsigned int lo = hv[w] & 0xFFFFu, hi = hv[w] >> 16;
        cur[w * 512 + tid] = run | ((run + lo) << 16);   // packed bucket starts
        run += lo + hi;
    }
    __syncthreads();

    // ---- pass B: re-read (L2 hit), scatter keys + indices ----
    for (int i = tid; i < NSAMP; i += RT) {
        unsigned int u = __float_as_uint(col[i]);
        unsigned int mono = u ^ ((u >> 31) ? 0xFFFFFFFFu : 0x80000000u);
        unsigned int k = ~mono;
        unsigned int b = k >> 18;
        unsigned int sh = (b & 1) * 16;
        unsigned int old = atomicAdd(&cur[cphys(b >> 1)], 1u << sh);
        int pos = (old >> sh) & 0xFFFF;
        keys[pos]  = k;
        order[pos] = (unsigned short)i;
    }
    __syncthreads();
    // cursors now hold bucket ENDS; start(b) = end(b-1), start(0) = 0.

    // ---- exact rank in sorted order (warp-coherent buckets, broadcast LDS) ----
    const float inv = 1.0f / (float)NSAMP;
    for (int p = tid; p < NSAMP; p += RT) {
        unsigned int k = keys[p];
        int i = order[p];
        unsigned int b = k >> 18;
        unsigned int we = cur[cphys(b >> 1)];
        int e = (we >> ((b & 1) * 16)) & 0xFFFF;
        int s = 0;
        if (b) {
            unsigned int b1 = b - 1;
            unsigned int ws2 = cur[cphys(b1 >> 1)];
            s = (ws2 >> ((b1 & 1) * 16)) & 0xFFFF;
        }
        int r = s;
        for (int q = s; q < e; ++q) {
            unsigned int kq = keys[q];           // broadcast (lanes share bucket)
            if (kq < k) r++;
            else if (kq == k) r += ((int)order[q] < i);
        }
        g_rank[(size_t)i * NCOL + c] = (float)r * inv;   // scattered, L2-absorbed
    }
}

// ---------------------------------------------------------------------------
// Kernel 3: per-sample stats + channel-127 conv (register-weight sliding
// accumulation) + leaky + linear. (R7-proven; vectorized xe/ws loads)
// ---------------------------------------------------------------------------
__global__ __launch_bounds__(320) void main_kernel(
    const float* __restrict__ x, const float* __restrict__ conv_w,
    const float* __restrict__ conv_b, const float* __restrict__ lin_w,
    const float* __restrict__ lin_b, float* __restrict__ out, int N)
{
    __shared__ float xe[59 * 8];          // rows 5..63 of first 8 features
    __shared__ float xc[WINDOW * IN_CH];  // assembled conv input [40][144]
    __shared__ float ws[IN_CH * KERNEL];  // conv_w[127]
    __shared__ float lw[LIN_IN];
    __shared__ float part[LIN_IN];
    __shared__ float part2[36 * 37];      // [t][chunk j], padded stride 37

    const int n   = blockIdx.x;
    const int tid = threadIdx.x;
    const float* xn = x + (size_t)n * (TDIM * FDIM);

    // ---- phase 1: loads (vectorized) ----
    {
        const float4* wsrc = (const float4*)(conv_w + 127 * IN_CH * KERNEL);
        for (int i = tid; i < IN_CH * KERNEL / 4; i += 320)
            ((float4*)ws)[i] = wsrc[i];
    }
    if (tid < LIN_IN) lw[tid] = lin_w[tid];

    if (tid < 118) {                       // 59 rows x 2 float4 halves
        int r = tid >> 1, h = tid & 1;
        *(float4*)&xe[r * 8 + h * 4] =
            *(const float4*)(xn + (5 + r) * FDIM + h * 4);
    }
    {   // raw channels: x[n, 24:64, 0:64] is 2560 contiguous floats
        const float4* src = (const float4*)(xn + 24 * FDIM);
        for (int q = tid; q < 640; q += 320) {
            float4 v = src[q];
            int l = q * 4;
            int t = l >> 6, i = l & 63;
            *(float4*)&xc[t * IN_CH + i] = v;
        }
    }
    {   // rank: coalesced 1280B read; feeds week (80..87) and month (120..127)
        float r = __ldg(&g_rank[(size_t)n * NCOL + tid]);
        int t = tid >> 3, f = tid & 7;
        xc[t * IN_CH + 80 + f]  = r;
        xc[t * IN_CH + 120 + f] = r;
    }
    __syncthreads();

    // ---- phase 2: sliding-window stats (thread = one (t,f) pair) ----
    {
        const int t = tid >> 3, f = tid & 7;
        float* row = &xc[t * IN_CH];
        float s = 0.f, s2 = 0.f, mx = -1e30f, mn = 1e30f;
        #pragma unroll
        for (int j = 0; j < 5; ++j) {
            float v = xe[(15 + t + j) * 8 + f];
            s += v; s2 = fmaf(v, v, s2);
            mx = fmaxf(mx, v); mn = fminf(mn, v);
        }
        row[64 + f] = s * 0.2f;
        row[72 + f] = sqrtf(fmaxf((s2 - s * s * 0.2f) * 0.25f, 0.f));
        row[88 + f] = mx;
        row[96 + f] = mn;
        s = 0.f; s2 = 0.f; mx = -1e30f; mn = 1e30f;
        #pragma unroll
        for (int j = 0; j < 20; ++j) {
            float v = xe[(t + j) * 8 + f];
            s += v; s2 = fmaf(v, v, s2);
            mx = fmaxf(mx, v); mn = fminf(mn, v);
        }
        row[104 + f] = s * 0.05f;
        row[112 + f] = sqrtf(fmaxf((s2 - s * s * 0.05f) * (1.0f / 19.0f), 0.f));
        row[128 + f] = mx;
        row[136 + f] = mn;
    }
    __syncthreads();

    // ---- phase 3: conv ch-127 via sliding accumulation ----
    // 144 threads: q = t-range quarter (9 outputs), j = float4 channel chunk.
    if (tid < 144) {
        const int q = tid / 36, j = tid - q * 36;
        float4 w4[KERNEL];
        #pragma unroll
        for (int k = 0; k < KERNEL; ++k) {
            w4[k].x = ws[(4 * j + 0) * KERNEL + k];
            w4[k].y = ws[(4 * j + 1) * KERNEL + k];
            w4[k].z = ws[(4 * j + 2) * KERNEL + k];
            w4[k].w = ws[(4 * j + 3) * KERNEL + k];
        }
        float acc[9];
        #pragma unroll
        for (int a = 0; a < 9; ++a) acc[a] = 0.f;
        const float4* xc4 = (const float4*)xc;
        const int r0 = 9 * q;
        #pragma unroll
        for (int rr = 0; rr < 13; ++rr) {
            float4 vv = xc4[(r0 + rr) * 36 + j];
            #pragma unroll
            for (int k = 0; k < KERNEL; ++k) {
                const int tt = rr - k;
                if (tt >= 0 && tt <= 8) {
                    acc[tt] = fmaf(w4[k].x, vv.x, acc[tt]);
                    acc[tt] = fmaf(w4[k].y, vv.y, acc[tt]);
                    acc[tt] = fmaf(w4[k].z, vv.z, acc[tt]);
                    acc[tt] = fmaf(w4[k].w, vv.w, acc[tt]);
                }
            }
        }
        #pragma unroll
        for (int a = 0; a < 9; ++a) part2[(r0 + a) * 37 + j] = acc[a];
    }
    __syncthreads();

    if (tid < LIN_IN) {
        float s = 0.f;
        #pragma unroll
        for (int j2 = 0; j2 < 36; ++j2) s += part2[tid * 37 + j2];
        s += conv_b[127];
        s = (s >= 0.0f) ? s : 0.01f * s;   // leaky ALPHA=0.01
        part[tid] = s * lw[tid];
    }
    __syncthreads();
    if (tid < 32) {
        float v = part[tid] + ((tid < 4) ? part[32 + tid] : 0.0f);
        #pragma unroll
        for (int d = 16; d > 0; d >>= 1)
            v += __shfl_down_sync(0xFFFFFFFFu, v, d);
        if (tid == 0) out[n] = v + lin_b[0];
    }
}

// ---------------------------------------------------------------------------
extern "C" void kernel_launch(void* const* d_in, const int* in_sizes, int n_in,
                              void* d_out, int out_size) {
    const float* x      = (const float*)d_in[0];
    const float* conv_w = (const float*)d_in[1];
    const float* conv_b = (const float*)d_in[2];
    const float* lin_w  = (const float*)d_in[3];
    const float* lin_b  = (const float*)d_in[4];
    float* out = (float*)d_out;
    const int N = in_sizes[0] / (TDIM * FDIM);   // 8000 (NSAMP)

    cudaFuncSetAttribute(rank_kernel, cudaFuncAttributeMaxDynamicSharedMemorySize, RANK_SMEM);

    dim3 gg((N + 255) / 256, WINDOW);
    gather_kernel<<<gg, 256>>>(x, N);
    rank_kernel<<<NCOL, RT, RANK_SMEM>>>();
    main_kernel<<<N, 320>>>(x, conv_w, conv_b, lin_w, lin_b, out, N);
}

// round 11
// speedup vs baseline: 1.8904x; 1.8904x over previous
#include <cuda_runtime.h>
#include <math.h>

// Problem constants
#define WINDOW 40
#define E 8
#define FDIM 64
#define TDIM 64
#define KERNEL 5
#define IN_CH 144          // F + 10*E
#define LIN_IN 36          // WINDOW + 1 - KERNEL
#define NCOL 320           // WINDOW * E rank columns
#define NMAX 8192

// Scratch (device globals — no allocation allowed)
__device__ float g_cols[(size_t)NCOL * NMAX];   // [col][n] gathered last-window values
__device__ float g_rankT[(size_t)NCOL * NMAX];  // [col][n] rank/N (coalesced writes)
__device__ float g_rank[(size_t)NMAX * NCOL];   // [n][col] rank/N (coalesced main reads)

// ---------------------------------------------------------------------------
// Kernel 1: gather x[:, 24+t, 0:8] -> g_cols[(t*8+f)][n]  (proven ~12us)
// ---------------------------------------------------------------------------
__global__ void gather_kernel(const float* __restrict__ x, int N) {
    __shared__ float tile[256][9];   // pad 9 -> conflict-free both phases
    const int t  = blockIdx.y;
    const int n0 = blockIdx.x * 256;
    const int tid = threadIdx.x;
    const int n = n0 + tid;
    if (n < N) {
        const float4* p = (const float4*)(x + (size_t)n * (TDIM * FDIM) + (24 + t) * FDIM);
        float4 a = p[0], b = p[1];
        tile[tid][0] = a.x; tile[tid][1] = a.y; tile[tid][2] = a.z; tile[tid][3] = a.w;
        tile[tid][4] = b.x; tile[tid][5] = b.y; tile[tid][6] = b.z; tile[tid][7] = b.w;
    }
    __syncthreads();
    #pragma unroll
    for (int idx = tid; idx < 8 * 256; idx += 256) {
        int f = idx >> 8, s = idx & 255;
        int nn = n0 + s;
        if (nn < N) g_cols[(size_t)(t * 8 + f) * NMAX + nn] = tile[s][f];
    }
}

// ---------------------------------------------------------------------------
// Kernel 2: exact stable descending rank (R3/R7-proven design).
// 15-bit bucket histogram -> padded conflict-free scan -> index scatter ->
// exact rank via tiny intra-bucket compare. Bit-exact vs argsort(argsort(-)).
// ---------------------------------------------------------------------------
#define RT 512
#define NBIN 32768                 // 15-bit buckets of the ascending key
#define HWORDS (NBIN / 2)          // 16384 packed u16-pair words
__device__ __forceinline__ int hphys(int W) { return W + (W >> 5); }
#define HPHYS (HWORDS + HWORDS / 32)   // 16896 words

// dynamic smem: keys u32[8192] | hist u32[HPHYS] | order u16[8192]
#define RANK_SMEM (32768 + HPHYS * 4 + 16384)

__global__ __launch_bounds__(RT) void rank_kernel(int N) {
    extern __shared__ unsigned char sm_raw[];
    unsigned int*   keys  = (unsigned int*)sm_raw;
    unsigned int*   hist  = (unsigned int*)(sm_raw + 32768);
    unsigned short* order = (unsigned short*)(sm_raw + 32768 + HPHYS * 4);
    __shared__ unsigned int aux2[16];

    const int c    = blockIdx.x;
    const int tid  = threadIdx.x;
    const int lane = tid & 31, wrp = tid >> 5;

    for (int i = tid; i < HPHYS; i += RT) hist[i] = 0u;
    __syncthreads();

    // load keys (coalesced from g_cols) + histogram
    const float* col = &g_cols[(size_t)c * NMAX];
    for (int i = tid; i < N; i += RT) {
        unsigned int u = __float_as_uint(col[i]);
        unsigned int mono = u ^ ((u >> 31) ? 0xFFFFFFFFu : 0x80000000u);
        unsigned int k = ~mono;                 // ascending k == descending value
        keys[i] = k;
        unsigned int b = k >> 17;               // top 15 bits
        atomicAdd(&hist[hphys(b >> 1)], 1u << ((b & 1) * 16));
    }
    __syncthreads();

    // exclusive scan over 32768 bins; thread owns 32 words (64 bins), padded
    const int base = tid * 33;
    unsigned int tsum = 0;
    #pragma unroll
    for (int w = 0; w < 32; ++w) {
        unsigned int v = hist[base + w];
        tsum += (v & 0xFFFFu) + (v >> 16);
    }
    unsigned int v = tsum;
    #pragma unroll
    for (int d = 1; d < 32; d <<= 1) {
        unsigned int t2 = __shfl_up_sync(0xFFFFFFFFu, v, d);
        if (lane >= d) v += t2;
    }
    if (lane == 31) aux2[wrp] = v;
    __syncthreads();
    if (wrp == 0 && lane < 16) {
        unsigned int s = aux2[lane];
        #pragma unroll
        for (int d = 1; d < 16; d <<= 1) {
            unsigned int t2 = __shfl_up_sync(0x0000FFFFu, s, d);
            if (lane >= d) s += t2;
        }
        aux2[lane] = s;
    }
    __syncthreads();
    unsigned int run = v - tsum + (wrp ? aux2[wrp - 1] : 0u);  // exclusive prefix
    #pragma unroll
    for (int w = 0; w < 32; ++w) {
        unsigned int pv = hist[base + w];
        unsigned int lo = pv & 0xFFFFu, hi = pv >> 16;
        hist[base + w] = run | ((run + lo) << 16);   // packed bucket-start cursors
        run += lo + hi;
    }
    __syncthreads();

    // scatter element indices into bucket-grouped order[]
    for (int i = tid; i < N; i += RT) {
        unsigned int b = keys[i] >> 17;
        unsigned int sh = (b & 1) * 16;
        unsigned int old = atomicAdd(&hist[hphys(b >> 1)], 1u << sh);
        order[(old >> sh) & 0xFFFFu] = (unsigned short)i;
    }
    __syncthreads();
    // cursors now hold bucket ENDS: end(b) = start(b+1)

    // exact rank: start-of-bucket + within-bucket compares (key, then index)
    const float inv = 1.0f / (float)N;
    float* dst = &g_rankT[(size_t)c * NMAX];
    for (int i = tid; i < N; i += RT) {
        unsigned int k = keys[i];
        unsigned int b = k >> 17;
        unsigned int we = hist[hphys(b >> 1)];
        int e = (we >> ((b & 1) * 16)) & 0xFFFF;
        int s = 0;
        if (b) {
            unsigned int b1 = b - 1;
            unsigned int ws2 = hist[hphys(b1 >> 1)];
            s = (ws2 >> ((b1 & 1) * 16)) & 0xFFFF;
        }
        int r = s;
        for (int p = s; p < e; ++p) {
            int j = order[p];
            unsigned int kj = keys[j];
            r += (kj < k) || (kj == k && j < i);
        }
        dst[i] = (float)r * inv;        // coalesced store
    }
}

// ---------------------------------------------------------------------------
// Kernel 3: transpose g_rankT[c][n] -> g_rank[n][c] (both sides coalesced)
// ---------------------------------------------------------------------------
__global__ void transpose_kernel(int N) {
    __shared__ float tile[32][33];
    const int c0 = blockIdx.x * 32;
    const int n0 = blockIdx.y * 32;
    const int tx = threadIdx.x, ty = threadIdx.y;   // 32 x 8
    #pragma unroll
    for (int j = ty; j < 32; j += 8) {
        int n = n0 + tx;
        if (n < N) tile[j][tx] = g_rankT[(size_t)(c0 + j) * NMAX + n];
    }
    __syncthreads();
    #pragma unroll
    for (int j = ty; j < 32; j += 8) {
        int n = n0 + j;
        if (n < N) g_rank[(size_t)n * NCOL + c0 + tx] = tile[tx][j];
    }
}

// ---------------------------------------------------------------------------
// Kernel 4: per-sample stats + channel-127 conv (register-weight sliding
// accumulation) + leaky + linear.  R7-proven body; ONLY change: minimum
// 5 blocks/SM (caps regs at 40) to lift occupancy on this latency-bound kernel.
// ---------------------------------------------------------------------------
__global__ __launch_bounds__(320, 5) void main_kernel(
    const float* __restrict__ x, const float* __restrict__ conv_w,
    const float* __restrict__ conv_b, const float* __restrict__ lin_w,
    const float* __restrict__ lin_b, float* __restrict__ out, int N)
{
    __shared__ float xe[59 * 8];          // rows 5..63 of first 8 features
    __shared__ float xc[WINDOW * IN_CH];  // assembled conv input [40][144]
    __shared__ float ws[IN_CH * KERNEL];  // conv_w[127]
    __shared__ float lw[LIN_IN];
    __shared__ float part[LIN_IN];
    __shared__ float part2[36 * 37];      // [t][chunk j], padded stride 37

    const int n   = blockIdx.x;
    const int tid = threadIdx.x;
    const float* xn = x + (size_t)n * (TDIM * FDIM);

    // ---- phase 1: loads ----
    for (int i = tid; i < IN_CH * KERNEL; i += 320) ws[i] = conv_w[127 * IN_CH * KERNEL + i];
    if (tid < LIN_IN) lw[tid] = lin_w[tid];

    for (int i = tid; i < 59 * 8; i += 320) {
        int r = i >> 3, f = i & 7;
        xe[i] = xn[(5 + r) * FDIM + f];
    }
    {   // raw channels: x[n, 24:64, 0:64] is 2560 contiguous floats
        const float4* src = (const float4*)(xn + 24 * FDIM);
        for (int q = tid; q < 640; q += 320) {
            float4 v = src[q];
            int l = q * 4;
            int t = l >> 6, i = l & 63;
            *(float4*)&xc[t * IN_CH + i] = v;
        }
    }
    {   // rank: coalesced 1280B block read; feeds week (80..87) and month (120..127)
        float r = __ldg(&g_rank[(size_t)n * NCOL + tid]);
        int t = tid >> 3, f = tid & 7;
        xc[t * IN_CH + 80 + f]  = r;
        xc[t * IN_CH + 120 + f] = r;
    }
    __syncthreads();

    // ---- phase 2: sliding-window stats (thread = one (t,f) pair) ----
    {
        const int t = tid >> 3, f = tid & 7;
        float* row = &xc[t * IN_CH];
        float s = 0.f, s2 = 0.f, mx = -1e30f, mn = 1e30f;
        #pragma unroll
        for (int j = 0; j < 5; ++j) {
            float v = xe[(15 + t + j) * 8 + f];
            s += v; s2 = fmaf(v, v, s2);
            mx = fmaxf(mx, v); mn = fminf(mn, v);
        }
        row[64 + f] = s * 0.2f;
        row[72 + f] = sqrtf(fmaxf((s2 - s * s * 0.2f) * 0.25f, 0.f));
        row[88 + f] = mx;
        row[96 + f] = mn;
        s = 0.f; s2 = 0.f; mx = -1e30f; mn = 1e30f;
        #pragma unroll
        for (int j = 0; j < 20; ++j) {
            float v = xe[(t + j) * 8 + f];
            s += v; s2 = fmaf(v, v, s2);
            mx = fmaxf(mx, v); mn = fminf(mn, v);
        }
        row[104 + f] = s * 0.05f;
        row[112 + f] = sqrtf(fmaxf((s2 - s * s * 0.05f) * (1.0f / 19.0f), 0.f));
        row[128 + f] = mx;
        row[136 + f] = mn;
    }
    __syncthreads();

    // ---- phase 3: conv ch-127 via sliding accumulation ----
    // 144 threads: q = t-range quarter (9 outputs), j = float4 channel chunk.
    if (tid < 144) {
        const int q = tid / 36, j = tid - q * 36;
        float4 w4[KERNEL];
        #pragma unroll
        for (int k = 0; k < KERNEL; ++k) {
            w4[k].x = ws[(4 * j + 0) * KERNEL + k];
            w4[k].y = ws[(4 * j + 1) * KERNEL + k];
            w4[k].z = ws[(4 * j + 2) * KERNEL + k];
            w4[k].w = ws[(4 * j + 3) * KERNEL + k];
        }
        float acc[9];
        #pragma unroll
        for (int a = 0; a < 9; ++a) acc[a] = 0.f;
        const float4* xc4 = (const float4*)xc;
        const int r0 = 9 * q;
        #pragma unroll
        for (int rr = 0; rr < 13; ++rr) {
            float4 vv = xc4[(r0 + rr) * 36 + j];
            #pragma unroll
            for (int k = 0; k < KERNEL; ++k) {
                const int tt = rr - k;
                if (tt >= 0 && tt <= 8) {
                    acc[tt] = fmaf(w4[k].x, vv.x, acc[tt]);
                    acc[tt] = fmaf(w4[k].y, vv.y, acc[tt]);
                    acc[tt] = fmaf(w4[k].z, vv.z, acc[tt]);
                    acc[tt] = fmaf(w4[k].w, vv.w, acc[tt]);
                }
            }
        }
        #pragma unroll
        for (int a = 0; a < 9; ++a) part2[(r0 + a) * 37 + j] = acc[a];
    }
    __syncthreads();

    if (tid < LIN_IN) {
        float s = 0.f;
        #pragma unroll
        for (int j2 = 0; j2 < 36; ++j2) s += part2[tid * 37 + j2];
        s += conv_b[127];
        s = (s >= 0.0f) ? s : 0.01f * s;   // leaky ALPHA=0.01
        part[tid] = s * lw[tid];
    }
    __syncthreads();
    if (tid < 32) {
        float v = part[tid] + ((tid < 4) ? part[32 + tid] : 0.0f);
        #pragma unroll
        for (int d = 16; d > 0; d >>= 1)
            v += __shfl_down_sync(0xFFFFFFFFu, v, d);
        if (tid == 0) out[n] = v + lin_b[0];
    }
}

// ---------------------------------------------------------------------------
extern "C" void kernel_launch(void* const* d_in, const int* in_sizes, int n_in,
                              void* d_out, int out_size) {
    const float* x      = (const float*)d_in[0];
    const float* conv_w = (const float*)d_in[1];
    const float* conv_b = (const float*)d_in[2];
    const float* lin_w  = (const float*)d_in[3];
    const float* lin_b  = (const float*)d_in[4];
    float* out = (float*)d_out;
    const int N = in_sizes[0] / (TDIM * FDIM);   // 8000

    cudaFuncSetAttribute(rank_kernel, cudaFuncAttributeMaxDynamicSharedMemorySize, RANK_SMEM);

    dim3 gg((N + 255) / 256, WINDOW);
    gather_kernel<<<gg, 256>>>(x, N);
    rank_kernel<<<NCOL, RT, RANK_SMEM>>>(N);
    dim3 tb(32, 8);
    dim3 tg(NCOL / 32, (N + 31) / 32);
    transpose_kernel<<<tg, tb>>>(N);
    main_kernel<<<N, 320>>>(x, conv_w, conv_b, lin_w, lin_b, out, N);
}